// round 1
// baseline (speedup 1.0000x reference)
#include <cuda_runtime.h>
#include <math.h>

// Problem constants
#define T_TOK 1024
#define HID   2048
#define IMID  1024          // routed expert intermediate
#define NEXP  16
#define TOPK  6
#define NPAIR (T_TOK * TOPK)   // 6144
#define ISH   2048          // shared expert intermediate (2 * I)
#define RSCALE 2.5f

// ---------------- scratch (device globals; no cudaMalloc allowed) ----------
__device__ float g_gu  [(size_t)NPAIR * 2 * IMID]; // routed gate_up out  [6144, 2048]
__device__ float g_hb  [(size_t)NPAIR * IMID];     // routed silu_mul     [6144, 1024]
__device__ float g_part[(size_t)NPAIR * HID];      // routed down out     [6144, 2048]
__device__ float g_gus [(size_t)T_TOK * 2 * ISH];  // shared gate_up out  [1024, 4096]
__device__ float g_hs  [(size_t)T_TOK * ISH];      // shared silu_mul     [1024, 2048]
__device__ float g_so  [(size_t)T_TOK * HID];      // shared down out     [1024, 2048]
__device__ int   g_cnt [NEXP];
__device__ int   g_list[NEXP * T_TOK];             // pair indices (t*6+slot) per expert
__device__ float g_tw  [T_TOK * TOPK];             // routing weights per (token, slot)

// ---------------- router ---------------------------------------------------
__global__ void zero_cnt_kernel(int* cnt) {
    if (threadIdx.x < NEXP) cnt[threadIdx.x] = 0;
}

__global__ void __launch_bounds__(256)
router_kernel(const float* __restrict__ X, const float* __restrict__ gw,
              const float* __restrict__ bias,
              int* __restrict__ cnt, int* __restrict__ list, float* __restrict__ tw)
{
    int t = blockIdx.x;
    __shared__ float red[NEXP * 256];
    float acc[NEXP];
#pragma unroll
    for (int e = 0; e < NEXP; e++) acc[e] = 0.f;

    const float* x = X + (size_t)t * HID;
    for (int h = threadIdx.x; h < HID; h += 256) {
        float xv = x[h];
#pragma unroll
        for (int e = 0; e < NEXP; e++) acc[e] += xv * gw[e * HID + h];
    }
#pragma unroll
    for (int e = 0; e < NEXP; e++) red[e * 256 + threadIdx.x] = acc[e];
    __syncthreads();
    for (int s = 128; s > 0; s >>= 1) {
        if (threadIdx.x < s) {
#pragma unroll
            for (int e = 0; e < NEXP; e++)
                red[e * 256 + threadIdx.x] += red[e * 256 + threadIdx.x + s];
        }
        __syncthreads();
    }

    if (threadIdx.x == 0) {
        float sc[NEXP], ch[NEXP];
#pragma unroll
        for (int e = 0; e < NEXP; e++) {
            float l = red[e * 256];
            float s = 1.f / (1.f + expf(-l));
            sc[e] = s;
            ch[e] = s + bias[e];
        }
        bool used[NEXP];
#pragma unroll
        for (int e = 0; e < NEXP; e++) used[e] = false;
        int sel[TOPK];
        float wsum = 0.f;
        for (int k = 0; k < TOPK; k++) {
            float best = -1e30f; int bi = 0;
            for (int e = 0; e < NEXP; e++) {
                if (!used[e] && ch[e] > best) { best = ch[e]; bi = e; }
            }
            used[bi] = true;
            sel[k] = bi;
            wsum += sc[bi];
        }
        float inv = RSCALE / wsum;
        for (int k = 0; k < TOPK; k++) {
            tw[t * TOPK + k] = sc[sel[k]] * inv;
            int pos = atomicAdd(&cnt[sel[k]], 1);
            list[sel[k] * T_TOK + pos] = t * TOPK + k;   // pair index
        }
    }
}

// ---------------- fp32 SGEMM (C = A @ B^T), both row-major K-contiguous ----
// Supports per-expert weight base (blockIdx.z), dynamic M via cnt[], and
// gather (A row = list[r]/adiv) / scatter (C row = list[r]).
#define BM 64
#define BN 64
#define BK 16

__global__ void __launch_bounds__(256)
gemm_nt(const float* __restrict__ A, const float* __restrict__ Bbase,
        float* __restrict__ C, int Mfixed, const int* __restrict__ cnt,
        int N, int K, const int* __restrict__ listBase, int adiv,
        long long bStride)
{
    int e = blockIdx.z;
    int M = cnt ? cnt[e] : Mfixed;
    int m0 = blockIdx.y * BM;
    if (m0 >= M) return;
    const int*   rows = listBase ? (listBase + e * T_TOK) : nullptr;
    const float* B    = Bbase + (long long)e * bStride;
    int n0 = blockIdx.x * BN;

    __shared__ float As[BK][BM];
    __shared__ float Bs[BK][BN];

    const int tid = threadIdx.x;
    const int lr = tid >> 2;           // 0..63  (row within tile to load)
    const int lk = (tid & 3) << 2;     // 0,4,8,12 (k offset to load)
    const int tx = tid & 15;
    const int ty = tid >> 4;

    int arow = m0 + lr;
    bool aval = arow < M;
    long long aoff;
    if (rows) {
        int p = aval ? rows[arow] : rows[0];
        aoff = (long long)(p / adiv) * K;
    } else {
        aoff = (long long)(aval ? arow : 0) * K;
    }
    const float4* Ap = (const float4*)(A + aoff + lk);
    const float4* Bp = (const float4*)(B + (long long)(n0 + lr) * K + lk);

    float acc[4][4];
#pragma unroll
    for (int i = 0; i < 4; i++)
#pragma unroll
        for (int j = 0; j < 4; j++) acc[i][j] = 0.f;

    float4 av = aval ? Ap[0] : make_float4(0.f, 0.f, 0.f, 0.f);
    float4 bv = Bp[0];

    for (int k0 = 0; k0 < K; k0 += BK) {
        As[lk + 0][lr] = av.x; As[lk + 1][lr] = av.y;
        As[lk + 2][lr] = av.z; As[lk + 3][lr] = av.w;
        Bs[lk + 0][lr] = bv.x; Bs[lk + 1][lr] = bv.y;
        Bs[lk + 2][lr] = bv.z; Bs[lk + 3][lr] = bv.w;
        __syncthreads();

        if (k0 + BK < K) {
            int kq = (k0 + BK) >> 2;   // float4 index
            av = aval ? Ap[kq] : make_float4(0.f, 0.f, 0.f, 0.f);
            bv = Bp[kq];
        }

#pragma unroll
        for (int kk = 0; kk < BK; kk++) {
            float4 a = *(const float4*)&As[kk][ty << 2];
            float4 b = *(const float4*)&Bs[kk][tx << 2];
            acc[0][0] = fmaf(a.x, b.x, acc[0][0]);
            acc[0][1] = fmaf(a.x, b.y, acc[0][1]);
            acc[0][2] = fmaf(a.x, b.z, acc[0][2]);
            acc[0][3] = fmaf(a.x, b.w, acc[0][3]);
            acc[1][0] = fmaf(a.y, b.x, acc[1][0]);
            acc[1][1] = fmaf(a.y, b.y, acc[1][1]);
            acc[1][2] = fmaf(a.y, b.z, acc[1][2]);
            acc[1][3] = fmaf(a.y, b.w, acc[1][3]);
            acc[2][0] = fmaf(a.z, b.x, acc[2][0]);
            acc[2][1] = fmaf(a.z, b.y, acc[2][1]);
            acc[2][2] = fmaf(a.z, b.z, acc[2][2]);
            acc[2][3] = fmaf(a.z, b.w, acc[2][3]);
            acc[3][0] = fmaf(a.w, b.x, acc[3][0]);
            acc[3][1] = fmaf(a.w, b.y, acc[3][1]);
            acc[3][2] = fmaf(a.w, b.z, acc[3][2]);
            acc[3][3] = fmaf(a.w, b.w, acc[3][3]);
        }
        __syncthreads();
    }

#pragma unroll
    for (int i = 0; i < 4; i++) {
        int r = m0 + (ty << 2) + i;
        if (r < M) {
            long long crow = rows ? rows[r] : r;
            float4 v = make_float4(acc[i][0], acc[i][1], acc[i][2], acc[i][3]);
            *(float4*)(C + crow * N + n0 + (tx << 2)) = v;
        }
    }
}

// ---------------- elementwise -----------------------------------------------
__device__ __forceinline__ float silu_f(float x) {
    return x / (1.f + expf(-x));
}

__global__ void silu_routed_kernel(const float* __restrict__ gu, float* __restrict__ hb)
{
    int idx = blockIdx.x * blockDim.x + threadIdx.x;   // NPAIR * IMID
    if (idx >= NPAIR * IMID) return;
    int p = idx >> 10;            // / IMID
    int i = idx & (IMID - 1);
    float g = gu[(size_t)p * (2 * IMID) + i];
    float u = gu[(size_t)p * (2 * IMID) + IMID + i];
    hb[idx] = silu_f(g) * u;
}

__global__ void silu_shared_kernel(const float* __restrict__ gus, float* __restrict__ hs)
{
    int idx = blockIdx.x * blockDim.x + threadIdx.x;   // T_TOK * ISH
    if (idx >= T_TOK * ISH) return;
    int p = idx >> 11;            // / ISH
    int i = idx & (ISH - 1);
    float g = gus[(size_t)p * (2 * ISH) + i];
    float u = gus[(size_t)p * (2 * ISH) + ISH + i];
    hs[idx] = silu_f(g) * u;
}

__global__ void combine_kernel(float* __restrict__ out,
                               const float* __restrict__ so,
                               const float* __restrict__ part,
                               const float* __restrict__ tw)
{
    int idx = blockIdx.x * blockDim.x + threadIdx.x;   // T_TOK * HID / 4
    if (idx >= T_TOK * HID / 4) return;
    int t = idx / (HID / 4);
    int c = (idx % (HID / 4)) * 4;
    float4 acc = *(const float4*)(so + (size_t)t * HID + c);
#pragma unroll
    for (int s = 0; s < TOPK; s++) {
        float w = tw[t * TOPK + s];
        float4 pv = *(const float4*)(part + (size_t)(t * TOPK + s) * HID + c);
        acc.x = fmaf(w, pv.x, acc.x);
        acc.y = fmaf(w, pv.y, acc.y);
        acc.z = fmaf(w, pv.z, acc.z);
        acc.w = fmaf(w, pv.w, acc.w);
    }
    *(float4*)(out + (size_t)t * HID + c) = acc;
}

// ---------------- launch ----------------------------------------------------
extern "C" void kernel_launch(void* const* d_in, const int* in_sizes, int n_in,
                              void* d_out, int out_size)
{
    (void)in_sizes; (void)n_in; (void)out_size;
    const float* X    = (const float*)d_in[0];  // [1024, 2048]
    const float* gw   = (const float*)d_in[1];  // [16, 2048]
    const float* bias = (const float*)d_in[2];  // [16]
    const float* w1   = (const float*)d_in[3];  // [16, 2048, 2048]
    const float* w2   = (const float*)d_in[4];  // [16, 2048, 1024]
    const float* sw1  = (const float*)d_in[5];  // [4096, 2048]
    const float* sw2  = (const float*)d_in[6];  // [2048, 2048]
    float* out = (float*)d_out;                 // [1024, 2048]

    float *p_gu, *p_hb, *p_part, *p_gus, *p_hs, *p_so, *p_tw;
    int *p_cnt, *p_list;
    cudaGetSymbolAddress((void**)&p_gu,   g_gu);
    cudaGetSymbolAddress((void**)&p_hb,   g_hb);
    cudaGetSymbolAddress((void**)&p_part, g_part);
    cudaGetSymbolAddress((void**)&p_gus,  g_gus);
    cudaGetSymbolAddress((void**)&p_hs,   g_hs);
    cudaGetSymbolAddress((void**)&p_so,   g_so);
    cudaGetSymbolAddress((void**)&p_tw,   g_tw);
    cudaGetSymbolAddress((void**)&p_cnt,  g_cnt);
    cudaGetSymbolAddress((void**)&p_list, g_list);

    // 1. router (builds per-expert pair lists + weights)
    zero_cnt_kernel<<<1, 32>>>(p_cnt);
    router_kernel<<<T_TOK, 256>>>(X, gw, bias, p_cnt, p_list, p_tw);

    // 2. shared expert path
    gemm_nt<<<dim3(2 * ISH / BN, T_TOK / BM, 1), 256>>>(
        X, sw1, p_gus, T_TOK, nullptr, 2 * ISH, HID, nullptr, 1, 0);
    silu_shared_kernel<<<(T_TOK * ISH + 255) / 256, 256>>>(p_gus, p_hs);
    gemm_nt<<<dim3(HID / BN, T_TOK / BM, 1), 256>>>(
        p_hs, sw2, p_so, T_TOK, nullptr, HID, ISH, nullptr, 1, 0);

    // 3. routed experts (grouped sparse GEMMs)
    gemm_nt<<<dim3(2 * IMID / BN, T_TOK / BM, NEXP), 256>>>(
        X, w1, p_gu, 0, p_cnt, 2 * IMID, HID, p_list, TOPK,
        (long long)(2 * IMID) * HID);
    silu_routed_kernel<<<(NPAIR * IMID + 255) / 256, 256>>>(p_gu, p_hb);
    gemm_nt<<<dim3(HID / BN, T_TOK / BM, NEXP), 256>>>(
        p_hb, w2, p_part, 0, p_cnt, HID, IMID, p_list, 1,
        (long long)HID * IMID);

    // 4. combine: out = shared + sum_slot w * partial
    combine_kernel<<<(T_TOK * HID / 4 + 255) / 256, 256>>>(out, p_so, p_part, p_tw);
}

// round 4
// speedup vs baseline: 3.2682x; 3.2682x over previous
#include <cuda_runtime.h>
#include <cuda_bf16.h>
#include <cstdint>
#include <math.h>

#define T_TOK 1024
#define HID   2048
#define IMID  1024
#define NEXP  16
#define TOPK  6
#define NPAIR (T_TOK * TOPK)
#define ISH   2048
#define RSCALE 2.5f

// ---------------- scratch ----------------
__device__ float g_hb [(size_t)NPAIR * IMID];   // routed h (post silu-mul) [6144,1024]
__device__ float g_hs [(size_t)T_TOK * ISH];    // shared h                 [1024,2048]
__device__ float g_part[(size_t)NPAIR * HID];   // routed down partials     [6144,2048]
__device__ float g_so [(size_t)T_TOK * HID];    // shared down out          [1024,2048]
__device__ int   g_cnt [NEXP];
__device__ int   g_list[NEXP * T_TOK];
__device__ float g_tw  [T_TOK * TOPK];

// ---------------- helpers ----------------
__device__ __forceinline__ uint32_t smem_u32(const void* p) {
    uint32_t a;
    asm("{ .reg .u64 t; cvta.to.shared.u64 t, %1; cvt.u32.u64 %0, t; }" : "=r"(a) : "l"(p));
    return a;
}
__device__ __forceinline__ uint32_t sw128(uint32_t off) { return off ^ ((off >> 3) & 0x70); }
__device__ __forceinline__ float silu_f(float x) { return x / (1.f + expf(-x)); }

#define LDSM4(r, addr) \
    asm volatile("ldmatrix.sync.aligned.m8n8.x4.shared.b16 {%0,%1,%2,%3}, [%4];" \
        : "=r"((r)[0]), "=r"((r)[1]), "=r"((r)[2]), "=r"((r)[3]) : "r"(addr))

__device__ __forceinline__ void mma_bf16(float* c, const uint32_t* a, const uint32_t* b) {
    asm volatile(
        "mma.sync.aligned.m16n8k16.row.col.f32.bf16.bf16.f32 "
        "{%0,%1,%2,%3}, {%4,%5,%6,%7}, {%8,%9}, {%0,%1,%2,%3};"
        : "+f"(c[0]), "+f"(c[1]), "+f"(c[2]), "+f"(c[3])
        : "r"(a[0]), "r"(a[1]), "r"(a[2]), "r"(a[3]), "r"(b[0]), "r"(b[1]));
}

// ---------------- router ----------------
__global__ void zero_cnt_kernel(int* cnt) { if (threadIdx.x < NEXP) cnt[threadIdx.x] = 0; }

__global__ void __launch_bounds__(256)
router_kernel(const float* __restrict__ X, const float* __restrict__ gw,
              const float* __restrict__ bias,
              int* __restrict__ cnt, int* __restrict__ list, float* __restrict__ tw)
{
    int t = blockIdx.x;
    __shared__ float red[NEXP * 256];
    float acc[NEXP];
#pragma unroll
    for (int e = 0; e < NEXP; e++) acc[e] = 0.f;
    const float* x = X + (size_t)t * HID;
    for (int h = threadIdx.x; h < HID; h += 256) {
        float xv = x[h];
#pragma unroll
        for (int e = 0; e < NEXP; e++) acc[e] += xv * gw[e * HID + h];
    }
#pragma unroll
    for (int e = 0; e < NEXP; e++) red[e * 256 + threadIdx.x] = acc[e];
    __syncthreads();
    for (int s = 128; s > 0; s >>= 1) {
        if (threadIdx.x < s) {
#pragma unroll
            for (int e = 0; e < NEXP; e++)
                red[e * 256 + threadIdx.x] += red[e * 256 + threadIdx.x + s];
        }
        __syncthreads();
    }
    if (threadIdx.x == 0) {
        float sc[NEXP], ch[NEXP];
#pragma unroll
        for (int e = 0; e < NEXP; e++) {
            float l = red[e * 256];
            float s = 1.f / (1.f + expf(-l));
            sc[e] = s; ch[e] = s + bias[e];
        }
        bool used[NEXP];
#pragma unroll
        for (int e = 0; e < NEXP; e++) used[e] = false;
        int sel[TOPK]; float wsum = 0.f;
        for (int k = 0; k < TOPK; k++) {
            float best = -1e30f; int bi = 0;
            for (int e = 0; e < NEXP; e++)
                if (!used[e] && ch[e] > best) { best = ch[e]; bi = e; }
            used[bi] = true; sel[k] = bi; wsum += sc[bi];
        }
        float inv = RSCALE / wsum;
        for (int k = 0; k < TOPK; k++) {
            tw[t * TOPK + k] = sc[sel[k]] * inv;
            int pos = atomicAdd(&cnt[sel[k]], 1);
            list[sel[k] * T_TOK + pos] = t * TOPK + k;
        }
    }
}

// ---------------- split-bf16 warp-MMA GEMM ----------------
// C[M,*] = A[M,K] @ B[rows,K]^T, fp32-ish accuracy via bf16 hi/lo (3 mma passes).
// B tile = 128 rows. FUSED: B rows interleave gate/up (even=gate, odd=up) so each
// thread's (c0,c1) = (gate,up) of one output col -> silu*mul in registers.
#define BM 128
#define BROWS 128
#define TILE_B 16384          // 128 rows * 64 bf16 * 2B
#define STAGE_B 65536         // Ahi, Alo, Bhi, Blo

template<bool FUSED>
__global__ void __launch_bounds__(256, 1)
mma_gemm(const float* __restrict__ A,
         const float* __restrict__ Bbase, long long bStride,
         float* __restrict__ C, int cStride, int upOff,
         int Mfixed, const int* __restrict__ cnt, int K,
         const int* __restrict__ list, int adiv)
{
    const int e = blockIdx.z;
    const int M = cnt ? cnt[e] : Mfixed;
    const int m0 = blockIdx.y * BM;
    if (m0 >= M) return;
    const int n0 = blockIdx.x;
    const float* B = Bbase + (size_t)e * bStride;
    const int* lst = list ? (list + e * T_TOK) : nullptr;

    extern __shared__ char dynraw[];
    char* dyn = (char*)(((uintptr_t)dynraw + 1023) & ~(uintptr_t)1023);
    const uint32_t dynu = smem_u32(dyn);

    __shared__ int s_aOff[BM];
    __shared__ int s_cRow[BM];
    __shared__ int s_bRow[BROWS];

    const int tid = threadIdx.x;
    const int lane = tid & 31;
    const int warp = tid >> 5;

    if (tid < BM) {
        int r = m0 + tid; if (r > M - 1) r = M - 1;
        int pr = lst ? lst[r] : r;
        s_cRow[tid] = pr;
        s_aOff[tid] = (lst ? pr / adiv : pr) * K;
        int bj;
        if (FUSED) bj = (tid >> 1) + n0 * 64 + ((tid & 1) ? upOff : 0);
        else       bj = n0 * BROWS + tid;
        s_bRow[tid] = bj;
    }
    __syncthreads();

    // ---- per-thread load slots: 16 x float4 (t<8 -> A, t>=8 -> B) ----
    int goff[16];
#pragma unroll
    for (int t = 0; t < 16; t++) {
        int id = t * 256 + tid;
        int row = (id >> 4) & 127;
        int c4 = id & 15;
        goff[t] = ((t < 8) ? s_aOff[row] : s_bRow[row] * K) + c4 * 4;
    }

    float4 v[16];
#pragma unroll
    for (int t = 0; t < 16; t++)
        v[t] = *(const float4*)(((t < 8) ? A : B) + goff[t]);

    // ---- warp compute layout: 4 warps along M (32 rows), 2 along N (64 B-rows) ----
    const int wm = warp & 3;
    const int wn = warp >> 2;
    const int aRow0 = wm * 32 + (lane & 7) + ((lane >> 3) & 1) * 8;
    const uint32_t aHi16 = ((lane >> 4) & 1) * 16;
    const uint32_t xorA = (uint32_t)(aRow0 & 7) << 4;
    const int bRow0 = wn * 64 + (lane & 7) + ((lane >> 4) & 1) * 8;
    const uint32_t bHi16 = ((lane >> 3) & 1) * 16;
    const uint32_t xorB = (uint32_t)(bRow0 & 7) << 4;

    float acc[2][8][4];
#pragma unroll
    for (int a = 0; a < 2; a++)
#pragma unroll
        for (int b = 0; b < 8; b++)
#pragma unroll
            for (int c = 0; c < 4; c++) acc[a][b][c] = 0.f;

    const int NC = K >> 6;
    for (int i = 0; i < NC; i++) {
        const int s = i & 1;
        char* sb = dyn + s * STAGE_B;

        // convert fp32 -> (hi, lo) bf16 and store to SMEM (sw128 swizzled)
#pragma unroll
        for (int t = 0; t < 16; t++) {
            int id = t * 256 + tid;
            int row = (id >> 4) & 127;
            int c4 = id & 15;
            uint32_t swo = ((t < 8) ? 0u : 2u * TILE_B) + sw128((uint32_t)(row * 128 + c4 * 8));
            float4 x = v[t];
            __nv_bfloat162 h01 = __floats2bfloat162_rn(x.x, x.y);
            __nv_bfloat162 h23 = __floats2bfloat162_rn(x.z, x.w);
            float r0 = x.x - __bfloat162float(h01.x);
            float r1 = x.y - __bfloat162float(h01.y);
            float r2 = x.z - __bfloat162float(h23.x);
            float r3 = x.w - __bfloat162float(h23.y);
            __nv_bfloat162 l01 = __floats2bfloat162_rn(r0, r1);
            __nv_bfloat162 l23 = __floats2bfloat162_rn(r2, r3);
            uint2 hw, lw;
            hw.x = *(uint32_t*)&h01; hw.y = *(uint32_t*)&h23;
            lw.x = *(uint32_t*)&l01; lw.y = *(uint32_t*)&l23;
            *(uint2*)(sb + swo) = hw;
            *(uint2*)(sb + swo + TILE_B) = lw;
        }
        __syncthreads();

        // prefetch next chunk while computing this one
        if (i + 1 < NC) {
            int k0 = (i + 1) << 6;
#pragma unroll
            for (int t = 0; t < 16; t++)
                v[t] = *(const float4*)(((t < 8) ? A : B) + goff[t] + k0);
        }

        const uint32_t su = dynu + s * STAGE_B;
#pragma unroll
        for (int ks = 0; ks < 4; ks++) {
            uint32_t aH[8], aL[8];
#pragma unroll
            for (int g = 0; g < 2; g++) {
                uint32_t ao = su + (uint32_t)(aRow0 + g * 16) * 128 +
                              (((uint32_t)ks * 32 + aHi16) ^ xorA);
                LDSM4(&aH[g * 4], ao);
                LDSM4(&aL[g * 4], ao + TILE_B);
            }
#pragma unroll
            for (int nh = 0; nh < 2; nh++) {
                uint32_t bH[8], bL[8];
#pragma unroll
                for (int q = 0; q < 2; q++) {
                    uint32_t bo = su + 2 * TILE_B +
                                  (uint32_t)(bRow0 + nh * 32 + q * 16) * 128 +
                                  (((uint32_t)ks * 32 + bHi16) ^ xorB);
                    LDSM4(&bH[q * 4], bo);
                    LDSM4(&bL[q * 4], bo + TILE_B);
                }
#pragma unroll
                for (int mi = 0; mi < 2; mi++) {
#pragma unroll
                    for (int ni = 0; ni < 4; ni++) {
                        float* c = acc[mi][nh * 4 + ni];
                        const uint32_t* bh = &bH[(ni >> 1) * 4 + (ni & 1) * 2];
                        const uint32_t* bl = &bL[(ni >> 1) * 4 + (ni & 1) * 2];
                        mma_bf16(c, &aH[mi * 4], bh);
                        mma_bf16(c, &aH[mi * 4], bl);
                        mma_bf16(c, &aL[mi * 4], bh);
                    }
                }
            }
        }
    }

    // ---- epilogue ----
#pragma unroll
    for (int mi = 0; mi < 2; mi++) {
#pragma unroll
        for (int nt = 0; nt < 8; nt++) {
            const float* c = acc[mi][nt];
            int rl0 = wm * 32 + mi * 16 + (lane >> 2);
            int rl1 = rl0 + 8;
            if (FUSED) {
                int col = n0 * 64 + wn * 32 + nt * 4 + (lane & 3);
                if (m0 + rl0 < M)
                    C[(size_t)s_cRow[rl0] * cStride + col] = silu_f(c[0]) * c[1];
                if (m0 + rl1 < M)
                    C[(size_t)s_cRow[rl1] * cStride + col] = silu_f(c[2]) * c[3];
            } else {
                int col = n0 * BROWS + wn * 64 + nt * 8 + 2 * (lane & 3);
                if (m0 + rl0 < M) {
                    float2 o; o.x = c[0]; o.y = c[1];
                    *(float2*)(C + (size_t)s_cRow[rl0] * cStride + col) = o;
                }
                if (m0 + rl1 < M) {
                    float2 o; o.x = c[2]; o.y = c[3];
                    *(float2*)(C + (size_t)s_cRow[rl1] * cStride + col) = o;
                }
            }
        }
    }
}

// ---------------- combine ----------------
__global__ void combine_kernel(float* __restrict__ out,
                               const float* __restrict__ so,
                               const float* __restrict__ part,
                               const float* __restrict__ tw)
{
    int idx = blockIdx.x * blockDim.x + threadIdx.x;
    if (idx >= T_TOK * HID / 4) return;
    int t = idx / (HID / 4);
    int c = (idx % (HID / 4)) * 4;
    float4 acc = *(const float4*)(so + (size_t)t * HID + c);
#pragma unroll
    for (int s = 0; s < TOPK; s++) {
        float w = tw[t * TOPK + s];
        float4 pv = *(const float4*)(part + (size_t)(t * TOPK + s) * HID + c);
        acc.x = fmaf(w, pv.x, acc.x);
        acc.y = fmaf(w, pv.y, acc.y);
        acc.z = fmaf(w, pv.z, acc.z);
        acc.w = fmaf(w, pv.w, acc.w);
    }
    *(float4*)(out + (size_t)t * HID + c) = acc;
}

// ---------------- launch ----------------
extern "C" void kernel_launch(void* const* d_in, const int* in_sizes, int n_in,
                              void* d_out, int out_size)
{
    (void)in_sizes; (void)n_in; (void)out_size;
    const float* X    = (const float*)d_in[0];
    const float* gw   = (const float*)d_in[1];
    const float* bias = (const float*)d_in[2];
    const float* w1   = (const float*)d_in[3];
    const float* w2   = (const float*)d_in[4];
    const float* sw1  = (const float*)d_in[5];
    const float* sw2  = (const float*)d_in[6];
    float* out = (float*)d_out;

    float *p_hb, *p_hs, *p_part, *p_so, *p_tw;
    int *p_cnt, *p_list;
    cudaGetSymbolAddress((void**)&p_hb,   g_hb);
    cudaGetSymbolAddress((void**)&p_hs,   g_hs);
    cudaGetSymbolAddress((void**)&p_part, g_part);
    cudaGetSymbolAddress((void**)&p_so,   g_so);
    cudaGetSymbolAddress((void**)&p_tw,   g_tw);
    cudaGetSymbolAddress((void**)&p_cnt,  g_cnt);
    cudaGetSymbolAddress((void**)&p_list, g_list);

    const size_t dynsm = 2 * STAGE_B + 1024;
    cudaFuncSetAttribute(mma_gemm<true>,  cudaFuncAttributeMaxDynamicSharedMemorySize, (int)dynsm);
    cudaFuncSetAttribute(mma_gemm<false>, cudaFuncAttributeMaxDynamicSharedMemorySize, (int)dynsm);

    // 1. router
    zero_cnt_kernel<<<1, 32>>>(p_cnt);
    router_kernel<<<T_TOK, 256>>>(X, gw, bias, p_cnt, p_list, p_tw);

    // 2. shared expert: fused gate_up + silu -> hs, then down -> so
    mma_gemm<true><<<dim3(ISH / 64, T_TOK / BM, 1), 256, dynsm>>>(
        X, sw1, 0, p_hs, ISH, ISH, T_TOK, nullptr, HID, nullptr, 1);
    mma_gemm<false><<<dim3(HID / BROWS, T_TOK / BM, 1), 256, dynsm>>>(
        p_hs, sw2, 0, p_so, HID, 0, T_TOK, nullptr, ISH, nullptr, 1);

    // 3. routed experts: fused gate_up + silu -> hb, then down -> partials
    mma_gemm<true><<<dim3(IMID / 64, 8, NEXP), 256, dynsm>>>(
        X, w1, (long long)(2 * IMID) * HID, p_hb, IMID, IMID,
        0, p_cnt, HID, p_list, TOPK);
    mma_gemm<false><<<dim3(HID / BROWS, 8, NEXP), 256, dynsm>>>(
        p_hb, w2, (long long)HID * IMID, p_part, HID, 0,
        0, p_cnt, IMID, p_list, 1);

    // 4. combine
    combine_kernel<<<(T_TOK * HID / 4 + 255) / 256, 256>>>(out, p_so, p_part, p_tw);
}

// round 5
// speedup vs baseline: 3.4516x; 1.0561x over previous
#include <cuda_runtime.h>
#include <cuda_bf16.h>
#include <cstdint>
#include <math.h>

#define T_TOK 1024
#define HID   2048
#define IMID  1024
#define NEXP  16
#define TOPK  6
#define NPAIR (T_TOK * TOPK)
#define ISH   2048
#define RSCALE 2.5f

// ---------------- scratch ----------------
__device__ float g_hb [(size_t)NPAIR * IMID];
__device__ float g_hs [(size_t)T_TOK * ISH];
__device__ float g_part[(size_t)NPAIR * HID];
__device__ float g_so [(size_t)T_TOK * HID];
__device__ int   g_cnt [NEXP];
__device__ int   g_list[NEXP * T_TOK];
__device__ float g_tw  [T_TOK * TOPK];

// ---------------- helpers ----------------
__device__ __forceinline__ uint32_t smem_u32(const void* p) {
    uint32_t a;
    asm("{ .reg .u64 t; cvta.to.shared.u64 t, %1; cvt.u32.u64 %0, t; }" : "=r"(a) : "l"(p));
    return a;
}
__device__ __forceinline__ float silu_f(float x) { return x / (1.f + expf(-x)); }

#define LDSM4(r, addr) \
    asm volatile("ldmatrix.sync.aligned.m8n8.x4.shared.b16 {%0,%1,%2,%3}, [%4];" \
        : "=r"((r)[0]), "=r"((r)[1]), "=r"((r)[2]), "=r"((r)[3]) : "r"(addr))

__device__ __forceinline__ void mma_bf16(float* c, const uint32_t* a, const uint32_t* b) {
    asm volatile(
        "mma.sync.aligned.m16n8k16.row.col.f32.bf16.bf16.f32 "
        "{%0,%1,%2,%3}, {%4,%5,%6,%7}, {%8,%9}, {%0,%1,%2,%3};"
        : "+f"(c[0]), "+f"(c[1]), "+f"(c[2]), "+f"(c[3])
        : "r"(a[0]), "r"(a[1]), "r"(a[2]), "r"(a[3]), "r"(b[0]), "r"(b[1]));
}

// named barriers (count = 384: 256 consumers + 128 producers)
#define NTHR 384
#define BAR_SYNC(id)   asm volatile("bar.sync %0, %1;"   :: "r"(id), "r"(NTHR) : "memory")
#define BAR_ARRIVE(id) asm volatile("bar.arrive %0, %1;" :: "r"(id), "r"(NTHR) : "memory")
// ids: 1 = full0, 2 = full1, 3 = empty0, 4 = empty1

// ---------------- router ----------------
__global__ void zero_cnt_kernel(int* cnt) { if (threadIdx.x < NEXP) cnt[threadIdx.x] = 0; }

__global__ void __launch_bounds__(256)
router_kernel(const float* __restrict__ X, const float* __restrict__ gw,
              const float* __restrict__ bias,
              int* __restrict__ cnt, int* __restrict__ list, float* __restrict__ tw)
{
    int t = blockIdx.x;
    __shared__ float red[NEXP * 256];
    float acc[NEXP];
#pragma unroll
    for (int e = 0; e < NEXP; e++) acc[e] = 0.f;
    const float* x = X + (size_t)t * HID;
    for (int h = threadIdx.x; h < HID; h += 256) {
        float xv = x[h];
#pragma unroll
        for (int e = 0; e < NEXP; e++) acc[e] += xv * gw[e * HID + h];
    }
#pragma unroll
    for (int e = 0; e < NEXP; e++) red[e * 256 + threadIdx.x] = acc[e];
    __syncthreads();
    for (int s = 128; s > 0; s >>= 1) {
        if (threadIdx.x < s) {
#pragma unroll
            for (int e = 0; e < NEXP; e++)
                red[e * 256 + threadIdx.x] += red[e * 256 + threadIdx.x + s];
        }
        __syncthreads();
    }
    if (threadIdx.x == 0) {
        float sc[NEXP], ch[NEXP];
#pragma unroll
        for (int e = 0; e < NEXP; e++) {
            float l = red[e * 256];
            float s = 1.f / (1.f + expf(-l));
            sc[e] = s; ch[e] = s + bias[e];
        }
        bool used[NEXP];
#pragma unroll
        for (int e = 0; e < NEXP; e++) used[e] = false;
        int sel[TOPK]; float wsum = 0.f;
        for (int k = 0; k < TOPK; k++) {
            float best = -1e30f; int bi = 0;
            for (int e = 0; e < NEXP; e++)
                if (!used[e] && ch[e] > best) { best = ch[e]; bi = e; }
            used[bi] = true; sel[k] = bi; wsum += sc[bi];
        }
        float inv = RSCALE / wsum;
        for (int k = 0; k < TOPK; k++) {
            tw[t * TOPK + k] = sc[sel[k]] * inv;
            int pos = atomicAdd(&cnt[sel[k]], 1);
            list[sel[k] * T_TOK + pos] = t * TOPK + k;
        }
    }
}

// ---------------- warp-specialized split-bf16 MMA GEMM ----------------
// 8 consumer warps (MMA) + 4 producer warps (LDG->cvt->STS), 2-stage SMEM pipe.
#define BM 128
#define BROWS 128
#define TILE_B 16384
#define STAGE_B 65536

template<bool FUSED>
__global__ void __launch_bounds__(NTHR, 1)
mma_gemm(const float* __restrict__ A,
         const float* __restrict__ Bbase, long long bStride,
         float* __restrict__ C, int cStride, int upOff,
         int Mfixed, const int* __restrict__ cnt, int K,
         const int* __restrict__ list, int adiv)
{
    const int e = blockIdx.z;
    const int M = cnt ? cnt[e] : Mfixed;
    const int m0 = blockIdx.y * BM;
    if (m0 >= M) return;
    const int n0 = blockIdx.x;
    const float* B = Bbase + (size_t)e * bStride;
    const int* lst = list ? (list + e * T_TOK) : nullptr;

    extern __shared__ char dynraw[];
    char* dyn = (char*)(((uintptr_t)dynraw + 1023) & ~(uintptr_t)1023);
    const uint32_t dynu = smem_u32(dyn);

    __shared__ int s_aOff[BM];
    __shared__ int s_cRow[BM];
    __shared__ int s_bRow[BROWS];

    const int tid = threadIdx.x;
    const int lane = tid & 31;
    const int warp = tid >> 5;

    if (tid < BM) {
        int r = m0 + tid; if (r > M - 1) r = M - 1;
        int pr = lst ? lst[r] : r;
        s_cRow[tid] = pr;
        s_aOff[tid] = (lst ? pr / adiv : pr) * K;
        int bj;
        if (FUSED) bj = (tid >> 1) + n0 * 64 + ((tid & 1) ? upOff : 0);
        else       bj = n0 * BROWS + tid;
        s_bRow[tid] = bj;
    }
    __syncthreads();

    const int NC = K >> 6;

    if (warp >= 8) {
        // ================= PRODUCER (warps 8..11, 128 threads) =================
        const int ptid = tid - 256;
        const int pr8 = ptid >> 4;          // 0..7 (base row)
        const int pc4 = ptid & 15;          // float4 column

        // slot s in [0,32): rows pr8 + 8*(s&15); s<16 -> A, else B
        for (int i = 0; i < NC; i++) {
            const int s = i & 1;
            if (i >= 2) BAR_SYNC(3 + s);            // wait empty
            char* sb = dyn + s * STAGE_B;
            const int k0 = i << 6;

            float4 va[8], vb[8];

            // load group helper (unrolled manually; slot constexpr-resolvable)
#define LOADG(gidx, vv)                                                          \
            _Pragma("unroll")                                                    \
            for (int j = 0; j < 8; j++) {                                        \
                const int slot = (gidx) * 8 + j;                                 \
                const int row = pr8 + 8 * (slot & 15);                           \
                const int off = (slot < 16) ? s_aOff[row]                        \
                                            : (s_bRow[row] * K);                 \
                (vv)[j] = *(const float4*)(((slot < 16) ? A : B) + off +         \
                                           pc4 * 4 + k0);                        \
            }
#define STOREG(gidx, vv)                                                         \
            _Pragma("unroll")                                                    \
            for (int j = 0; j < 8; j++) {                                        \
                const int slot = (gidx) * 8 + j;                                 \
                const int row = pr8 + 8 * (slot & 15);                           \
                uint32_t swz = (uint32_t)(row * 128 + pc4 * 8);                  \
                swz ^= (uint32_t)(row & 7) << 4;                                 \
                uint32_t o = ((slot < 16) ? 0u : 2u * TILE_B) + swz;             \
                float4 x = (vv)[j];                                              \
                __nv_bfloat162 h01 = __floats2bfloat162_rn(x.x, x.y);            \
                __nv_bfloat162 h23 = __floats2bfloat162_rn(x.z, x.w);            \
                float r0 = x.x - __bfloat162float(h01.x);                        \
                float r1 = x.y - __bfloat162float(h01.y);                        \
                float r2 = x.z - __bfloat162float(h23.x);                        \
                float r3 = x.w - __bfloat162float(h23.y);                        \
                __nv_bfloat162 l01 = __floats2bfloat162_rn(r0, r1);              \
                __nv_bfloat162 l23 = __floats2bfloat162_rn(r2, r3);              \
                uint2 hw, lw;                                                    \
                hw.x = *(uint32_t*)&h01; hw.y = *(uint32_t*)&h23;                \
                lw.x = *(uint32_t*)&l01; lw.y = *(uint32_t*)&l23;                \
                *(uint2*)(sb + o) = hw;                                          \
                *(uint2*)(sb + o + TILE_B) = lw;                                 \
            }

            LOADG(0, va)
            LOADG(1, vb) STOREG(0, va)
            LOADG(2, va) STOREG(1, vb)
            LOADG(3, vb) STOREG(2, va)
            STOREG(3, vb)
#undef LOADG
#undef STOREG
            BAR_ARRIVE(1 + s);                      // signal full
        }
        return;
    }

    // ================= CONSUMER (warps 0..7) =================
    const int wm = warp & 3;
    const int wn = warp >> 2;
    const int aRow0 = wm * 32 + (lane & 7) + ((lane >> 3) & 1) * 8;
    const uint32_t aHi16 = ((lane >> 4) & 1) * 16;
    const uint32_t xorA = (uint32_t)(aRow0 & 7) << 4;
    const int bRow0 = wn * 64 + (lane & 7) + ((lane >> 4) & 1) * 8;
    const uint32_t bHi16 = ((lane >> 3) & 1) * 16;
    const uint32_t xorB = (uint32_t)(bRow0 & 7) << 4;

    float acc[2][8][4];
#pragma unroll
    for (int a = 0; a < 2; a++)
#pragma unroll
        for (int b = 0; b < 8; b++)
#pragma unroll
            for (int c = 0; c < 4; c++) acc[a][b][c] = 0.f;

    for (int i = 0; i < NC; i++) {
        const int s = i & 1;
        BAR_SYNC(1 + s);                            // wait full
        const uint32_t su = dynu + s * STAGE_B;
#pragma unroll
        for (int ks = 0; ks < 4; ks++) {
            uint32_t aH[8], aL[8];
#pragma unroll
            for (int g = 0; g < 2; g++) {
                uint32_t ao = su + (uint32_t)(aRow0 + g * 16) * 128 +
                              (((uint32_t)ks * 32 + aHi16) ^ xorA);
                LDSM4(&aH[g * 4], ao);
                LDSM4(&aL[g * 4], ao + TILE_B);
            }
#pragma unroll
            for (int nh = 0; nh < 2; nh++) {
                uint32_t bH[8], bL[8];
#pragma unroll
                for (int q = 0; q < 2; q++) {
                    uint32_t bo = su + 2 * TILE_B +
                                  (uint32_t)(bRow0 + nh * 32 + q * 16) * 128 +
                                  (((uint32_t)ks * 32 + bHi16) ^ xorB);
                    LDSM4(&bH[q * 4], bo);
                    LDSM4(&bL[q * 4], bo + TILE_B);
                }
#pragma unroll
                for (int mi = 0; mi < 2; mi++) {
#pragma unroll
                    for (int ni = 0; ni < 4; ni++) {
                        float* c = acc[mi][nh * 4 + ni];
                        const uint32_t* bh = &bH[(ni >> 1) * 4 + (ni & 1) * 2];
                        const uint32_t* bl = &bL[(ni >> 1) * 4 + (ni & 1) * 2];
                        mma_bf16(c, &aH[mi * 4], bh);
                        mma_bf16(c, &aH[mi * 4], bl);
                        mma_bf16(c, &aL[mi * 4], bh);
                    }
                }
            }
        }
        if (i + 2 < NC) BAR_ARRIVE(3 + s);          // signal empty
    }

    // ---- epilogue ----
#pragma unroll
    for (int mi = 0; mi < 2; mi++) {
#pragma unroll
        for (int nt = 0; nt < 8; nt++) {
            const float* c = acc[mi][nt];
            int rl0 = wm * 32 + mi * 16 + (lane >> 2);
            int rl1 = rl0 + 8;
            if (FUSED) {
                int col = n0 * 64 + wn * 32 + nt * 4 + (lane & 3);
                if (m0 + rl0 < M)
                    C[(size_t)s_cRow[rl0] * cStride + col] = silu_f(c[0]) * c[1];
                if (m0 + rl1 < M)
                    C[(size_t)s_cRow[rl1] * cStride + col] = silu_f(c[2]) * c[3];
            } else {
                int col = n0 * BROWS + wn * 64 + nt * 8 + 2 * (lane & 3);
                if (m0 + rl0 < M) {
                    float2 o; o.x = c[0]; o.y = c[1];
                    *(float2*)(C + (size_t)s_cRow[rl0] * cStride + col) = o;
                }
                if (m0 + rl1 < M) {
                    float2 o; o.x = c[2]; o.y = c[3];
                    *(float2*)(C + (size_t)s_cRow[rl1] * cStride + col) = o;
                }
            }
        }
    }
}

// ---------------- combine ----------------
__global__ void combine_kernel(float* __restrict__ out,
                               const float* __restrict__ so,
                               const float* __restrict__ part,
                               const float* __restrict__ tw)
{
    int idx = blockIdx.x * blockDim.x + threadIdx.x;
    if (idx >= T_TOK * HID / 4) return;
    int t = idx / (HID / 4);
    int c = (idx % (HID / 4)) * 4;
    float4 acc = *(const float4*)(so + (size_t)t * HID + c);
#pragma unroll
    for (int s = 0; s < TOPK; s++) {
        float w = tw[t * TOPK + s];
        float4 pv = *(const float4*)(part + (size_t)(t * TOPK + s) * HID + c);
        acc.x = fmaf(w, pv.x, acc.x);
        acc.y = fmaf(w, pv.y, acc.y);
        acc.z = fmaf(w, pv.z, acc.z);
        acc.w = fmaf(w, pv.w, acc.w);
    }
    *(float4*)(out + (size_t)t * HID + c) = acc;
}

// ---------------- launch ----------------
extern "C" void kernel_launch(void* const* d_in, const int* in_sizes, int n_in,
                              void* d_out, int out_size)
{
    (void)in_sizes; (void)n_in; (void)out_size;
    const float* X    = (const float*)d_in[0];
    const float* gw   = (const float*)d_in[1];
    const float* bias = (const float*)d_in[2];
    const float* w1   = (const float*)d_in[3];
    const float* w2   = (const float*)d_in[4];
    const float* sw1  = (const float*)d_in[5];
    const float* sw2  = (const float*)d_in[6];
    float* out = (float*)d_out;

    float *p_hb, *p_hs, *p_part, *p_so, *p_tw;
    int *p_cnt, *p_list;
    cudaGetSymbolAddress((void**)&p_hb,   g_hb);
    cudaGetSymbolAddress((void**)&p_hs,   g_hs);
    cudaGetSymbolAddress((void**)&p_part, g_part);
    cudaGetSymbolAddress((void**)&p_so,   g_so);
    cudaGetSymbolAddress((void**)&p_tw,   g_tw);
    cudaGetSymbolAddress((void**)&p_cnt,  g_cnt);
    cudaGetSymbolAddress((void**)&p_list, g_list);

    const size_t dynsm = 2 * STAGE_B + 1024;
    cudaFuncSetAttribute(mma_gemm<true>,  cudaFuncAttributeMaxDynamicSharedMemorySize, (int)dynsm);
    cudaFuncSetAttribute(mma_gemm<false>, cudaFuncAttributeMaxDynamicSharedMemorySize, (int)dynsm);

    // 1. router
    zero_cnt_kernel<<<1, 32>>>(p_cnt);
    router_kernel<<<T_TOK, 256>>>(X, gw, bias, p_cnt, p_list, p_tw);

    // 2. shared expert
    mma_gemm<true><<<dim3(ISH / 64, T_TOK / BM, 1), NTHR, dynsm>>>(
        X, sw1, 0, p_hs, ISH, ISH, T_TOK, nullptr, HID, nullptr, 1);
    mma_gemm<false><<<dim3(HID / BROWS, T_TOK / BM, 1), NTHR, dynsm>>>(
        p_hs, sw2, 0, p_so, HID, 0, T_TOK, nullptr, ISH, nullptr, 1);

    // 3. routed experts
    mma_gemm<true><<<dim3(IMID / 64, 8, NEXP), NTHR, dynsm>>>(
        X, w1, (long long)(2 * IMID) * HID, p_hb, IMID, IMID,
        0, p_cnt, HID, p_list, TOPK);
    mma_gemm<false><<<dim3(HID / BROWS, 8, NEXP), NTHR, dynsm>>>(
        p_hb, w2, (long long)HID * IMID, p_part, HID, 0,
        0, p_cnt, IMID, p_list, 1);

    // 4. combine
    combine_kernel<<<(T_TOK * HID / 4 + 255) / 256, 256>>>(out, p_so, p_part, p_tw);
}